// round 14
// baseline (speedup 1.0000x reference)
#include <cuda_runtime.h>

// SoftmaxProbs: mean = (1/B) * sum_{b,c} l[b,c] * (lse_b - x[b,c])
// 2M rows x 18 classes fp32, HBM-bound (288 MB).
// R10 structure (warp-owned slices, batched label LDG.128) + 3-STAGE cp.async
// pipeline (wait_group 2): two x-stages per warp in flight at all times.
// BLK=128 so 3 buffers fit in static smem; 8 blocks/SM.

#define NC 18
#define BLK 128
#define NWARP (BLK / 32)
#define NSTG 3
#define RPW 32                        // rows per warp per chunk
#define WF  (RPW * NC)                // 576 floats per warp-slice
#define WV4 (WF / 4)                  // 144 float4 per warp-slice
#define MAX_GRID 2048

__device__ double       g_partials[MAX_GRID];
__device__ unsigned int g_count = 0;

__device__ __forceinline__ void cpa16(unsigned int saddr, const float4* g) {
    asm volatile("cp.async.cg.shared.global [%0], [%1], 16;" :: "r"(saddr), "l"(g));
}
__device__ __forceinline__ void cpa_commit() {
    asm volatile("cp.async.commit_group;");
}

__global__ __launch_bounds__(BLK, 8)
void ce_main_kernel(const float* __restrict__ x,
                    const float* __restrict__ lab,
                    float* __restrict__ out,
                    int B, int nchunks)
{
    __shared__ float  sx[NSTG][NWARP][WF];   // 3*4*576*4 = 27648 B
    __shared__ float  rowlse[NWARP][RPW];    // 512 B
    __shared__ double sred[NWARP];
    __shared__ int    s_last;

    const int tid  = threadIdx.x;
    const int w    = tid >> 5;
    const int lane = tid & 31;

    // Stage this warp's 32-row slice of chunk c into sx[s][w].
    auto stage_w = [&](int c, int s) {
        const long long r0 = (long long)c * BLK + (long long)w * RPW;
        long long rem = (long long)B - r0;
        if (rem <= 0) return;
        const int wr = rem < RPW ? (int)rem : RPW;
        const float* xb = x + r0 * NC;
        if (wr == RPW) {
            const float4* xb4 = (const float4*)xb;   // 16B-aligned (2304B slices)
            const unsigned sxa = (unsigned)__cvta_generic_to_shared(&sx[s][w][0]);
            #pragma unroll
            for (int j = 0; j < 4; j++)
                cpa16(sxa + (lane + j * 32) * 16, xb4 + lane + j * 32);
            if (lane < WV4 - 128)                    // last 16 float4: lanes 0..15
                cpa16(sxa + (lane + 128) * 16, xb4 + lane + 128);
        } else {                                     // rare tail: scalar STS
            const int nf = wr * NC;
            for (int i = lane; i < nf; i += 32)
                sx[s][w][i] = xb[i];
        }
    };

    const int c0 = blockIdx.x;
    const int g  = gridDim.x;
    double acc = 0.0;

    // Prologue: two stages in flight before first compute.
    stage_w(c0, 0);       cpa_commit();
    stage_w(c0 + g, 1);   cpa_commit();

    int it = 0;
    for (int c = c0; c < nchunks; c += g, it++) {
        const int stg = it % NSTG;

        // Keep pipeline full: stage chunk c + 2g into the buffer freed last iter.
        const int nxt2 = c + 2 * g;
        if (nxt2 < nchunks) stage_w(nxt2, (it + 2) % NSTG);
        cpa_commit();
        asm volatile("cp.async.wait_group 2;");      // chunk c's slice resident
        __syncwarp();

        const long long r0 = (long long)c * BLK + (long long)w * RPW;
        long long rem = (long long)B - r0;
        const int wr = rem <= 0 ? 0 : (rem < RPW ? (int)rem : RPW);

        // ── Phase 1: per-row LSE (72 B stride LDS: conflict-free) ──
        if (lane < wr) {
            const float* rx = &sx[stg][w][lane * NC];
            float xr[NC];
            #pragma unroll
            for (int k = 0; k < NC; k++) xr[k] = rx[k];
            float m = xr[0];
            #pragma unroll
            for (int k = 1; k < NC; k++) m = fmaxf(m, xr[k]);
            float s = 0.f;
            #pragma unroll
            for (int k = 0; k < NC; k++) s += __expf(xr[k] - m);
            rowlse[w][lane] = m + __logf(s);
        }
        __syncwarp();

        // ── Phase 2: labels via batched LDG.128, elementwise l*(lse-x) ──
        float f0 = 0.f, f1 = 0.f, f2 = 0.f, f3 = 0.f;
        const float* lb = lab + r0 * NC;

        auto consume = [&](float4 lv, int i) {
            const float4 xv = ((const float4*)&sx[stg][w][0])[i];
            const int e = i << 2;
            f0 += lv.x * (rowlse[w][(e    ) / NC] - xv.x);
            f1 += lv.y * (rowlse[w][(e + 1) / NC] - xv.y);
            f2 += lv.z * (rowlse[w][(e + 2) / NC] - xv.z);
            f3 += lv.w * (rowlse[w][(e + 3) / NC] - xv.w);
        };

        if (wr == RPW) {
            const float4* lb4 = (const float4*)lb;
            float4 L0 = lb4[lane      ];
            float4 L1 = lb4[lane +  32];
            float4 L2 = lb4[lane +  64];
            float4 L3 = lb4[lane +  96];
            float4 L4;
            const bool has5 = lane < (WV4 - 128);    // lanes 0..15
            if (has5) L4 = lb4[lane + 128];

            consume(L0, lane      );
            consume(L1, lane +  32);
            consume(L2, lane +  64);
            consume(L3, lane +  96);
            if (has5) consume(L4, lane + 128);
        } else if (wr > 0) {                         // rare tail
            const int nf = wr * NC;
            for (int i = lane; i < nf; i += 32)
                f0 += lb[i] * (rowlse[w][i / NC] - sx[stg][w][i]);
        }
        acc += (double)((f0 + f1) + (f2 + f3));
        __syncwarp();                                // buffer reusable for restage
    }
    asm volatile("cp.async.wait_group 0;");

    // ── per-warp then per-block deterministic reduction ──
    #pragma unroll
    for (int o = 16; o > 0; o >>= 1)
        acc += __shfl_down_sync(0xffffffffu, acc, o);
    if (lane == 0) sred[w] = acc;
    __syncthreads();

    if (tid == 0) {
        double v = 0.0;
        #pragma unroll
        for (int i = 0; i < NWARP; i++) v += sred[i];
        g_partials[blockIdx.x] = v;
        __threadfence();
        unsigned prev = atomicAdd(&g_count, 1u);
        s_last = (prev == gridDim.x - 1u) ? 1 : 0;
    }
    __syncthreads();

    // ── fused finalize: last block sums all partials ──
    if (s_last) {
        double v = 0.0;
        for (int i = tid; i < (int)gridDim.x; i += BLK)
            v += g_partials[i];
        #pragma unroll
        for (int o = 16; o > 0; o >>= 1)
            v += __shfl_down_sync(0xffffffffu, v, o);
        if (lane == 0) sred[w] = v;
        __syncthreads();
        if (tid == 0) {
            double t = 0.0;
            #pragma unroll
            for (int i = 0; i < NWARP; i++) t += sred[i];
            out[0] = (float)(t / (double)B);
            g_count = 0;                             // reset for next graph replay
        }
    }
}

extern "C" void kernel_launch(void* const* d_in, const int* in_sizes, int n_in,
                              void* d_out, int out_size)
{
    const float* x   = (const float*)d_in[0];   // output       [B, 18]
    const float* lab = (const float*)d_in[1];   // labels_soft  [B, 18]
    const int B = in_sizes[0] / NC;
    const int nchunks = (B + BLK - 1) / BLK;    // B=2e6 -> 15625 full chunks

    int grid = 148 * 8;                 // 8 blocks/SM (27.7 KB smem, 64 regs)
    if (grid > nchunks) grid = nchunks;
    if (grid < 1) grid = 1;
    if (grid > MAX_GRID) grid = MAX_GRID;

    ce_main_kernel<<<grid, BLK>>>(x, lab, (float*)d_out, B, nchunks);
}